// round 13
// baseline (speedup 1.0000x reference)
#include <cuda_runtime.h>
#include <stdint.h>

// ---------------------------------------------------------------------------
// PGExplainer forward: masked_adj = adj * 0.5*(mask + mask^T)
// out[c,r] = cnt(c,r) * 0.5 * (S(c,r) + S(r,c)),  S = sum of sampled values
// Hash table keyed by cell id (c*N+r): sums (direct), tsums (fed by the
// transpose edge), cnts. Edge (c,r) adds v to sums[slot(c,r)] AND
// tsums[slot(r,c)] => final write is probe-free and idempotent.
// ---------------------------------------------------------------------------

#define N_NODES 10000
#define N_EDGES 640000
#define D_EMB   128
#define HID     64

#define OUT_ELEMS ((size_t)N_NODES * N_NODES)   // 1e8 floats = 400 MB
#define OUT_F4    (OUT_ELEMS / 4)               // 25,000,000 float4

#define HCAP  (1 << 21)
#define HMASK (HCAP - 1)
#define HCAP4 (HCAP / 4)

// ---- k_prep block partition (R8 shape, measured 30.7us) ----
#define PRE_HALF_BLOCKS 313                      // ceil(10000/32)
#define PRE_BLOCKS      (2 * PRE_HALF_BLOCKS)    // 626
#define DEC_BLOCKS      ((N_EDGES + 255) / 256)  // 2500
#define PREP_BLOCKS     (PRE_BLOCKS + DEC_BLOCKS)

// ---- k_fused2: zero blocks FIRST, edge blocks behind them ----
#define ZERO_BLOCKS  12500
#define ZPB4         2000                        // 12500 * 2000 = 25M exact
#define EDGE_BLOCKS  2500                        // 256 edges each
#define FUSED_BLOCKS (ZERO_BLOCKS + EDGE_BLOCKS)

// ---- k_sym2: 4 edges per thread ----
#define SYM_THREADS  (N_EDGES / 4)               // 160,000
#define SYM_BLOCKS   (SYM_THREADS / 256)         // 625

// Scratch (device globals; hash table cleared in k_prep every call).
__device__ float g_A[N_NODES * HID];
__device__ float g_B[N_NODES * HID];
__device__ float g_noise[N_EDGES];
__device__ int2  g_ci[N_EDGES];
__device__ int   g_slot[N_EDGES];
__device__ int   g_keys[HCAP];          // -1 = empty
__device__ float g_sums[HCAP];          // S at slot(c,r)
__device__ float g_tsums[HCAP];         // at slot(c,r): sum of v over edges (r,c)
__device__ int   g_cnts[HCAP];

__device__ __forceinline__ uint32_t cell_hash(int key) {
    return ((uint32_t)key * 0x9E3779B1u) >> (32 - 21);
}

__device__ __forceinline__ uint32_t probe_slot(int key) {
    uint32_t h = cell_hash(key);
    while (true) {
        int k = g_keys[h];
        if (k == key) break;
        if (k == -1) {
            int old = atomicCAS(&g_keys[h], -1, key);
            if (old == -1 || old == key) break;
        }
        h = (h + 1) & HMASK;
    }
    return h;
}

// ---------------------------------------------------------------------------
// threefry2x32 (JAX schedule), key = (0, 42); partitionable stream.
// ---------------------------------------------------------------------------
__device__ __forceinline__ uint32_t rotl32(uint32_t x, int d) {
    return (x << d) | (x >> (32 - d));
}

__device__ __forceinline__ void threefry2x32(uint32_t k0, uint32_t k1,
                                             uint32_t x0, uint32_t x1,
                                             uint32_t& o0, uint32_t& o1) {
    uint32_t ks0 = k0, ks1 = k1, ks2 = k0 ^ k1 ^ 0x1BD11BDAu;
#define TF_R4(a, b, c, d)                            \
    x0 += x1; x1 = rotl32(x1, a); x1 ^= x0;          \
    x0 += x1; x1 = rotl32(x1, b); x1 ^= x0;          \
    x0 += x1; x1 = rotl32(x1, c); x1 ^= x0;          \
    x0 += x1; x1 = rotl32(x1, d); x1 ^= x0;
    x0 += ks0; x1 += ks1;
    TF_R4(13, 15, 26, 6);  x0 += ks1; x1 += ks2 + 1u;
    TF_R4(17, 29, 16, 24); x0 += ks2; x1 += ks0 + 2u;
    TF_R4(13, 15, 26, 6);  x0 += ks0; x1 += ks1 + 3u;
    TF_R4(17, 29, 16, 24); x0 += ks1; x1 += ks2 + 4u;
    TF_R4(13, 15, 26, 6);  x0 += ks2; x1 += ks0 + 5u;
#undef TF_R4
    o0 = x0; o1 = x1;
}

__device__ __forceinline__ float noise_from_bits(uint32_t bits) {
    float u = __uint_as_float((bits >> 9) | 0x3f800000u) - 1.0f;   // [0,1)
    return logf(u) - log1pf(-u);   // u==0 -> -inf -> sigmoid -> 0
}

// ---------------------------------------------------------------------------
// K_prep (R8 shape): [0,626) GEMM tiles | [626,3126) decode+noise+table clear.
// ---------------------------------------------------------------------------
__global__ void __launch_bounds__(256) k_prep(const float* __restrict__ embed,
                                              const float* __restrict__ W1,
                                              const void* __restrict__ ei_raw) {
    __shared__ float es[32 * D_EMB];                  // 16 KB
    __shared__ int   s_flag;

    if (blockIdx.x < PRE_BLOCKS) {
        int half = blockIdx.x >= PRE_HALF_BLOCKS;
        int nb   = blockIdx.x - half * PRE_HALF_BLOCKS;
        int n0   = nb * 32;
        int hq   = threadIdx.x & 15;
        int gp   = threadIdx.x >> 4;

        const float4* emb4 = (const float4*)embed;
        size_t ebase = (size_t)n0 * (D_EMB / 4);
        float4* es4 = (float4*)es;
        #pragma unroll
        for (int i = 0; i < 4; i++) {
            size_t gidx = ebase + threadIdx.x + i * 256;
            if (gidx < (size_t)N_NODES * (D_EMB / 4))
                es4[threadIdx.x + i * 256] = emb4[gidx];
        }
        __syncthreads();

        const float4* W14 = (const float4*)(W1 + (size_t)half * D_EMB * HID);
        float4 a0 = make_float4(0.f, 0.f, 0.f, 0.f);
        float4 a1 = make_float4(0.f, 0.f, 0.f, 0.f);
        const float* er0 = es + (gp * 2)     * D_EMB;
        const float* er1 = es + (gp * 2 + 1) * D_EMB;
        #pragma unroll 8
        for (int d = 0; d < D_EMB; d++) {
            float4 w  = __ldg(&W14[d * 16 + hq]);
            float  e0 = er0[d];
            float  e1 = er1[d];
            a0.x = fmaf(e0, w.x, a0.x); a0.y = fmaf(e0, w.y, a0.y);
            a0.z = fmaf(e0, w.z, a0.z); a0.w = fmaf(e0, w.w, a0.w);
            a1.x = fmaf(e1, w.x, a1.x); a1.y = fmaf(e1, w.y, a1.y);
            a1.z = fmaf(e1, w.z, a1.z); a1.w = fmaf(e1, w.w, a1.w);
        }
        float4* dst = half ? (float4*)g_B : (float4*)g_A;
        int n = n0 + gp * 2;
        if (n < N_NODES)     dst[n * 16 + hq]       = a0;
        if (n + 1 < N_NODES) dst[(n + 1) * 16 + hq] = a1;
        return;
    }

    // ---------------- decode + noise + table clear ----------------
    {
        int bidx = blockIdx.x - PRE_BLOCKS;
        int e    = bidx * 256 + threadIdx.x;

        // inline dtype detect over a fixed 32KB window (same answer per block)
        if (threadIdx.x == 0) s_flag = 0;
        __syncthreads();
        const uint32_t* ew = (const uint32_t*)ei_raw;
        int nz = 0;
        #pragma unroll
        for (int i = 0; i < 16; i++)
            nz |= (ew[2 * (threadIdx.x + i * 256) + 1] != 0u);
        if (nz) s_flag = 1;
        __syncthreads();
        int is64 = s_flag ? 0 : 1;

        // hash table clear (int4 slabs; 2500*256 = 640000 > HCAP4 = 524288)
        if (e < HCAP4) {
            ((int4*)g_keys)[e]    = make_int4(-1, -1, -1, -1);
            ((float4*)g_sums)[e]  = make_float4(0.f, 0.f, 0.f, 0.f);
            ((float4*)g_tsums)[e] = make_float4(0.f, 0.f, 0.f, 0.f);
            ((int4*)g_cnts)[e]    = make_int4(0, 0, 0, 0);
        }

        if (e >= N_EDGES) return;
        int c, r;
        if (is64) {
            const long long* p = (const long long*)ei_raw;
            c = (int)p[e];
            r = (int)p[N_EDGES + e];
        } else {
            const int* p = (const int*)ei_raw;
            c = p[e];
            r = p[N_EDGES + e];
        }
        c = min(max(c, 0), N_NODES - 1);
        r = min(max(r, 0), N_NODES - 1);
        g_ci[e] = make_int2(c, r);

        uint32_t o0, o1;
        threefry2x32(0u, 42u, 0u, (uint32_t)e, o0, o1);
        g_noise[e] = noise_from_bits(o0 ^ o1);
    }
}

// ---------------------------------------------------------------------------
// K_fused2: zero blocks FIRST (pure streaming stores, 4.5 TB/s shape), edge
// blocks LAST (they fill vacated SM slots and overlap the store drain).
// ---------------------------------------------------------------------------
__global__ void __launch_bounds__(256) k_fused2(const float* __restrict__ b1,
                                                const float* __restrict__ W2,
                                                const float* __restrict__ b2,
                                                float4* __restrict__ out) {
    if (blockIdx.x < ZERO_BLOCKS) {
        // ---------------- pure zero blocks ----------------
        const float4 z4 = make_float4(0.f, 0.f, 0.f, 0.f);
        size_t zbase = (size_t)blockIdx.x * ZPB4;
        #pragma unroll
        for (int i = 0; i < 7; i++)
            __stcs(&out[zbase + threadIdx.x + i * 256], z4);
        if (threadIdx.x < ZPB4 - 7 * 256)
            __stcs(&out[zbase + threadIdx.x + 7 * 256], z4);
        return;
    }

    // ---------------- edge blocks: 256 edges each ----------------
    int warp = threadIdx.x >> 5;
    int lane = threadIdx.x & 31;
    int grp  = lane >> 3;          // edge slot within warp (0..3)
    int l8   = lane & 7;           // h-octet

    const float4* b14 = (const float4*)b1;
    const float4* w24 = (const float4*)W2;
    float4 b1a = __ldg(&b14[l8 * 2]);
    float4 b1b = __ldg(&b14[l8 * 2 + 1]);
    float4 w2a = __ldg(&w24[l8 * 2]);
    float4 w2b = __ldg(&w24[l8 * 2 + 1]);
    float  bias2 = __ldg(&b2[0]);

    const float4* A4 = (const float4*)g_A;
    const float4* B4 = (const float4*)g_B;

    int ebase = (blockIdx.x - ZERO_BLOCKS) * 256 + warp * 4 + grp;
    #pragma unroll 2
    for (int it = 0; it < 8; it++) {
        int e = ebase + it * 32;
        int2 cr = g_ci[e];

        float4 av0 = A4[cr.x * 16 + l8 * 2];
        float4 av1 = A4[cr.x * 16 + l8 * 2 + 1];
        float4 bv0 = B4[cr.y * 16 + l8 * 2];
        float4 bv1 = B4[cr.y * 16 + l8 * 2 + 1];

        float s;
        s  = fmaxf(av0.x + bv0.x + b1a.x, 0.f) * w2a.x;
        s += fmaxf(av0.y + bv0.y + b1a.y, 0.f) * w2a.y;
        s += fmaxf(av0.z + bv0.z + b1a.z, 0.f) * w2a.z;
        s += fmaxf(av0.w + bv0.w + b1a.w, 0.f) * w2a.w;
        s += fmaxf(av1.x + bv1.x + b1b.x, 0.f) * w2b.x;
        s += fmaxf(av1.y + bv1.y + b1b.y, 0.f) * w2b.y;
        s += fmaxf(av1.z + bv1.z + b1b.z, 0.f) * w2b.z;
        s += fmaxf(av1.w + bv1.w + b1b.w, 0.f) * w2b.w;

        // reduce across the 8 lanes of this edge group (result on all lanes)
        s += __shfl_xor_sync(0xffffffffu, s, 1);
        s += __shfl_xor_sync(0xffffffffu, s, 2);
        s += __shfl_xor_sync(0xffffffffu, s, 4);

        // all lanes compute v redundantly (noise load broadcasts)
        float x = g_noise[e] + s + bias2;
        float v = 1.0f / (1.0f + expf(-x));   // sigmoid; -inf -> 0 exactly

        // dual insert: lane 0 -> direct cell, lane 1 -> transpose cell
        if (l8 == 0) {
            uint32_t h = probe_slot(cr.x * N_NODES + cr.y);
            atomicAdd(&g_sums[h], v);
            atomicAdd(&g_cnts[h], 1);
            g_slot[e] = (int)h;
        } else if (l8 == 1) {
            uint32_t h2 = probe_slot(cr.y * N_NODES + cr.x);
            atomicAdd(&g_tsums[h2], v);
        }
    }
}

// ---------------------------------------------------------------------------
// K_sym2: probe-free, 4 edges per thread (ILP):
//   out[c,r] = cnt * 0.5 * (S + T)       (idempotent streaming store)
// ---------------------------------------------------------------------------
__global__ void __launch_bounds__(256) k_sym2(float* __restrict__ out) {
    int t = blockIdx.x * blockDim.x + threadIdx.x;

    int   e[4];
    int2  cr[4];
    int   sl[4];
    #pragma unroll
    for (int i = 0; i < 4; i++) {
        e[i]  = t + i * SYM_THREADS;
        cr[i] = __ldg(&g_ci[e[i]]);
        sl[i] = __ldg(&g_slot[e[i]]);
    }
    float S[4], T[4];
    int   C[4];
    #pragma unroll
    for (int i = 0; i < 4; i++) {
        S[i] = g_sums[sl[i]];
        T[i] = g_tsums[sl[i]];
        C[i] = g_cnts[sl[i]];
    }
    #pragma unroll
    for (int i = 0; i < 4; i++) {
        __stcs(&out[(size_t)cr[i].x * N_NODES + cr[i].y],
               (float)C[i] * 0.5f * (S[i] + T[i]));
    }
}

// ---------------------------------------------------------------------------
extern "C" void kernel_launch(void* const* d_in, const int* in_sizes, int n_in,
                              void* d_out, int out_size) {
    const float* embed = (const float*)d_in[0];
    const void*  ei    = d_in[1];
    const float* W1    = (const float*)d_in[2];
    const float* b1    = (const float*)d_in[3];
    const float* W2    = (const float*)d_in[4];
    const float* b2    = (const float*)d_in[5];
    float*       out   = (float*)d_out;

    // 1. prep: node GEMM halves | decode+noise+table clear
    k_prep<<<PREP_BLOCKS, 256>>>(embed, W1, ei);

    // 2. zero (first, pure) + edge MLP/sample/dual-insert (last, overlapped)
    k_fused2<<<FUSED_BLOCKS, 256>>>(b1, W2, b2, (float4*)out);

    // 3. probe-free symmetrize -> idempotent streaming stores
    k_sym2<<<SYM_BLOCKS, 256>>>(out);
}

// round 14
// speedup vs baseline: 1.3073x; 1.3073x over previous
#include <cuda_runtime.h>
#include <stdint.h>

// ---------------------------------------------------------------------------
// PGExplainer forward: masked_adj = adj * 0.5*(mask + mask^T)
// out[c,r] = cnt(c,r) * 0.5 * (S(c,r) + S(r,c)),  S = sum of sampled values
// Graph shape (stream fork/join):
//   chain A: k_zero (400 MB streaming zero of d_out)
//   chain B: k_prep (GEMM halves | decode+noise+table clear) -> k_edge
//   join   : k_sym (probe transpose, idempotent stores)
// ---------------------------------------------------------------------------

#define N_NODES 10000
#define N_EDGES 640000
#define D_EMB   128
#define HID     64

#define OUT_ELEMS ((size_t)N_NODES * N_NODES)   // 1e8 floats = 400 MB
#define OUT_F4    (OUT_ELEMS / 4)               // 25,000,000 float4

#define HCAP  (1 << 21)
#define HMASK (HCAP - 1)
#define HCAP4 (HCAP / 4)

// ---- k_zero ----
#define ZERO_BLOCKS  12500
#define ZPB4         2000                        // 12500 * 2000 = 25M exact

// ---- k_prep (R8 shape, measured ~31us) ----
#define PRE_HALF_BLOCKS 313
#define PRE_BLOCKS      (2 * PRE_HALF_BLOCKS)    // 626
#define DEC_BLOCKS      ((N_EDGES + 255) / 256)  // 2500
#define PREP_BLOCKS     (PRE_BLOCKS + DEC_BLOCKS)

// ---- k_edge ----
#define EDGE_BLOCKS  2500                        // 256 edges each

// ---- k_sym: 4 edges per thread ----
#define SYM_THREADS  (N_EDGES / 4)               // 160,000
#define SYM_BLOCKS   (SYM_THREADS / 256)         // 625

// Scratch (device globals; hash table cleared in k_prep every call).
__device__ float g_A[N_NODES * HID];
__device__ float g_B[N_NODES * HID];
__device__ float g_noise[N_EDGES];
__device__ int2  g_ci[N_EDGES];
__device__ int   g_slot[N_EDGES];
__device__ int   g_keys[HCAP];          // -1 = empty
__device__ float g_sums[HCAP];
__device__ int   g_cnts[HCAP];

__device__ __forceinline__ uint32_t cell_hash(int key) {
    return ((uint32_t)key * 0x9E3779B1u) >> (32 - 21);
}

__device__ __forceinline__ uint32_t probe_slot(int key) {
    uint32_t h = cell_hash(key);
    while (true) {
        int k = g_keys[h];
        if (k == key) break;
        if (k == -1) {
            int old = atomicCAS(&g_keys[h], -1, key);
            if (old == -1 || old == key) break;
        }
        h = (h + 1) & HMASK;
    }
    return h;
}

// ---------------------------------------------------------------------------
// threefry2x32 (JAX schedule), key = (0, 42); partitionable stream.
// ---------------------------------------------------------------------------
__device__ __forceinline__ uint32_t rotl32(uint32_t x, int d) {
    return (x << d) | (x >> (32 - d));
}

__device__ __forceinline__ void threefry2x32(uint32_t k0, uint32_t k1,
                                             uint32_t x0, uint32_t x1,
                                             uint32_t& o0, uint32_t& o1) {
    uint32_t ks0 = k0, ks1 = k1, ks2 = k0 ^ k1 ^ 0x1BD11BDAu;
#define TF_R4(a, b, c, d)                            \
    x0 += x1; x1 = rotl32(x1, a); x1 ^= x0;          \
    x0 += x1; x1 = rotl32(x1, b); x1 ^= x0;          \
    x0 += x1; x1 = rotl32(x1, c); x1 ^= x0;          \
    x0 += x1; x1 = rotl32(x1, d); x1 ^= x0;
    x0 += ks0; x1 += ks1;
    TF_R4(13, 15, 26, 6);  x0 += ks1; x1 += ks2 + 1u;
    TF_R4(17, 29, 16, 24); x0 += ks2; x1 += ks0 + 2u;
    TF_R4(13, 15, 26, 6);  x0 += ks0; x1 += ks1 + 3u;
    TF_R4(17, 29, 16, 24); x0 += ks1; x1 += ks2 + 4u;
    TF_R4(13, 15, 26, 6);  x0 += ks2; x1 += ks0 + 5u;
#undef TF_R4
    o0 = x0; o1 = x1;
}

__device__ __forceinline__ float noise_from_bits(uint32_t bits) {
    float u = __uint_as_float((bits >> 9) | 0x3f800000u) - 1.0f;   // [0,1)
    return logf(u) - log1pf(-u);   // u==0 -> -inf -> sigmoid -> 0
}

// ---------------------------------------------------------------------------
// K_zero: pure streaming zero of d_out (chain A).
// ---------------------------------------------------------------------------
__global__ void __launch_bounds__(256) k_zero(float4* __restrict__ out) {
    const float4 z4 = make_float4(0.f, 0.f, 0.f, 0.f);
    size_t zbase = (size_t)blockIdx.x * ZPB4;
    #pragma unroll
    for (int i = 0; i < 7; i++)
        __stcs(&out[zbase + threadIdx.x + i * 256], z4);
    if (threadIdx.x < ZPB4 - 7 * 256)
        __stcs(&out[zbase + threadIdx.x + 7 * 256], z4);
}

// ---------------------------------------------------------------------------
// K_prep: [0,626) GEMM tiles | [626,3126) decode+noise+table clear (chain B).
// ---------------------------------------------------------------------------
__global__ void __launch_bounds__(256) k_prep(const float* __restrict__ embed,
                                              const float* __restrict__ W1,
                                              const void* __restrict__ ei_raw) {
    __shared__ float es[32 * D_EMB];                  // 16 KB
    __shared__ int   s_flag;

    if (blockIdx.x < PRE_BLOCKS) {
        int half = blockIdx.x >= PRE_HALF_BLOCKS;
        int nb   = blockIdx.x - half * PRE_HALF_BLOCKS;
        int n0   = nb * 32;
        int hq   = threadIdx.x & 15;
        int gp   = threadIdx.x >> 4;

        const float4* emb4 = (const float4*)embed;
        size_t ebase = (size_t)n0 * (D_EMB / 4);
        float4* es4 = (float4*)es;
        #pragma unroll
        for (int i = 0; i < 4; i++) {
            size_t gidx = ebase + threadIdx.x + i * 256;
            if (gidx < (size_t)N_NODES * (D_EMB / 4))
                es4[threadIdx.x + i * 256] = emb4[gidx];
        }
        __syncthreads();

        const float4* W14 = (const float4*)(W1 + (size_t)half * D_EMB * HID);
        float4 a0 = make_float4(0.f, 0.f, 0.f, 0.f);
        float4 a1 = make_float4(0.f, 0.f, 0.f, 0.f);
        const float* er0 = es + (gp * 2)     * D_EMB;
        const float* er1 = es + (gp * 2 + 1) * D_EMB;
        #pragma unroll 8
        for (int d = 0; d < D_EMB; d++) {
            float4 w  = __ldg(&W14[d * 16 + hq]);
            float  e0 = er0[d];
            float  e1 = er1[d];
            a0.x = fmaf(e0, w.x, a0.x); a0.y = fmaf(e0, w.y, a0.y);
            a0.z = fmaf(e0, w.z, a0.z); a0.w = fmaf(e0, w.w, a0.w);
            a1.x = fmaf(e1, w.x, a1.x); a1.y = fmaf(e1, w.y, a1.y);
            a1.z = fmaf(e1, w.z, a1.z); a1.w = fmaf(e1, w.w, a1.w);
        }
        float4* dst = half ? (float4*)g_B : (float4*)g_A;
        int n = n0 + gp * 2;
        if (n < N_NODES)     dst[n * 16 + hq]       = a0;
        if (n + 1 < N_NODES) dst[(n + 1) * 16 + hq] = a1;
        return;
    }

    // ---------------- decode + noise + table clear ----------------
    {
        int bidx = blockIdx.x - PRE_BLOCKS;
        int e    = bidx * 256 + threadIdx.x;

        if (threadIdx.x == 0) s_flag = 0;
        __syncthreads();
        const uint32_t* ew = (const uint32_t*)ei_raw;
        int nz = 0;
        #pragma unroll
        for (int i = 0; i < 16; i++)
            nz |= (ew[2 * (threadIdx.x + i * 256) + 1] != 0u);
        if (nz) s_flag = 1;
        __syncthreads();
        int is64 = s_flag ? 0 : 1;

        if (e < HCAP4) {
            ((int4*)g_keys)[e]   = make_int4(-1, -1, -1, -1);
            ((float4*)g_sums)[e] = make_float4(0.f, 0.f, 0.f, 0.f);
            ((int4*)g_cnts)[e]   = make_int4(0, 0, 0, 0);
        }

        if (e >= N_EDGES) return;
        int c, r;
        if (is64) {
            const long long* p = (const long long*)ei_raw;
            c = (int)p[e];
            r = (int)p[N_EDGES + e];
        } else {
            const int* p = (const int*)ei_raw;
            c = p[e];
            r = p[N_EDGES + e];
        }
        c = min(max(c, 0), N_NODES - 1);
        r = min(max(r, 0), N_NODES - 1);
        g_ci[e] = make_int2(c, r);

        uint32_t o0, o1;
        threefry2x32(0u, 42u, 0u, (uint32_t)e, o0, o1);
        g_noise[e] = noise_from_bits(o0 ^ o1);
    }
}

// ---------------------------------------------------------------------------
// K_edge: 256 edges/block, 8-lane groups, single insert (R7 body, chain B).
// ---------------------------------------------------------------------------
__global__ void __launch_bounds__(256) k_edge(const float* __restrict__ b1,
                                              const float* __restrict__ W2,
                                              const float* __restrict__ b2) {
    int warp = threadIdx.x >> 5;
    int lane = threadIdx.x & 31;
    int grp  = lane >> 3;
    int l8   = lane & 7;

    const float4* b14 = (const float4*)b1;
    const float4* w24 = (const float4*)W2;
    float4 b1a = __ldg(&b14[l8 * 2]);
    float4 b1b = __ldg(&b14[l8 * 2 + 1]);
    float4 w2a = __ldg(&w24[l8 * 2]);
    float4 w2b = __ldg(&w24[l8 * 2 + 1]);
    float  bias2 = __ldg(&b2[0]);

    const float4* A4 = (const float4*)g_A;
    const float4* B4 = (const float4*)g_B;

    int ebase = blockIdx.x * 256 + warp * 4 + grp;
    #pragma unroll 2
    for (int it = 0; it < 8; it++) {
        int e = ebase + it * 32;
        int2 cr = g_ci[e];

        float4 av0 = A4[cr.x * 16 + l8 * 2];
        float4 av1 = A4[cr.x * 16 + l8 * 2 + 1];
        float4 bv0 = B4[cr.y * 16 + l8 * 2];
        float4 bv1 = B4[cr.y * 16 + l8 * 2 + 1];

        float s;
        s  = fmaxf(av0.x + bv0.x + b1a.x, 0.f) * w2a.x;
        s += fmaxf(av0.y + bv0.y + b1a.y, 0.f) * w2a.y;
        s += fmaxf(av0.z + bv0.z + b1a.z, 0.f) * w2a.z;
        s += fmaxf(av0.w + bv0.w + b1a.w, 0.f) * w2a.w;
        s += fmaxf(av1.x + bv1.x + b1b.x, 0.f) * w2b.x;
        s += fmaxf(av1.y + bv1.y + b1b.y, 0.f) * w2b.y;
        s += fmaxf(av1.z + bv1.z + b1b.z, 0.f) * w2b.z;
        s += fmaxf(av1.w + bv1.w + b1b.w, 0.f) * w2b.w;

        s += __shfl_xor_sync(0xffffffffu, s, 1);
        s += __shfl_xor_sync(0xffffffffu, s, 2);
        s += __shfl_xor_sync(0xffffffffu, s, 4);

        if (l8 == 0) {
            float x = g_noise[e] + s + bias2;
            float v = 1.0f / (1.0f + expf(-x));   // sigmoid; -inf -> 0 exactly

            uint32_t h = probe_slot(cr.x * N_NODES + cr.y);
            atomicAdd(&g_sums[h], v);
            atomicAdd(&g_cnts[h], 1);
            g_slot[e] = (int)h;
        }
    }
}

// ---------------------------------------------------------------------------
// K_sym: 4 edges per thread (ILP), probe transpose, idempotent stores.
// ---------------------------------------------------------------------------
__global__ void __launch_bounds__(256) k_sym(float* __restrict__ out) {
    int t = blockIdx.x * blockDim.x + threadIdx.x;

    int2 cr[4];
    int  sl[4];
    #pragma unroll
    for (int i = 0; i < 4; i++) {
        int e = t + i * SYM_THREADS;
        cr[i] = __ldg(&g_ci[e]);
        sl[i] = __ldg(&g_slot[e]);
    }

    float S[4]; int C[4]; float ST[4];
    uint32_t h[4]; int tkey[4];
    #pragma unroll
    for (int i = 0; i < 4; i++) {
        S[i] = g_sums[sl[i]];
        C[i] = g_cnts[sl[i]];
        tkey[i] = cr[i].y * N_NODES + cr[i].x;
        h[i] = cell_hash(tkey[i]);
        ST[i] = 0.0f;
    }
    #pragma unroll
    for (int i = 0; i < 4; i++) {
        uint32_t hh = h[i];
        while (true) {
            int k = g_keys[hh];
            if (k == tkey[i]) { ST[i] = g_sums[hh]; break; }
            if (k == -1) break;
            hh = (hh + 1) & HMASK;
        }
    }
    #pragma unroll
    for (int i = 0; i < 4; i++)
        __stcs(&out[(size_t)cr[i].x * N_NODES + cr[i].y],
               (float)C[i] * 0.5f * (S[i] + ST[i]));
}

// ---------------------------------------------------------------------------
// Host: fork/join stream pattern (capture-legal). Streams/events are plain
// host-side objects, created once and reused; no device memory is allocated.
// ---------------------------------------------------------------------------
static cudaStream_t g_s1 = nullptr;
static cudaEvent_t  g_ev_fork = nullptr;
static cudaEvent_t  g_ev_join = nullptr;

extern "C" void kernel_launch(void* const* d_in, const int* in_sizes, int n_in,
                              void* d_out, int out_size) {
    const float* embed = (const float*)d_in[0];
    const void*  ei    = d_in[1];
    const float* W1    = (const float*)d_in[2];
    const float* b1    = (const float*)d_in[3];
    const float* W2    = (const float*)d_in[4];
    const float* b2    = (const float*)d_in[5];
    float*       out   = (float*)d_out;

    if (g_s1 == nullptr) {
        cudaStreamCreateWithFlags(&g_s1, cudaStreamNonBlocking);
        cudaEventCreateWithFlags(&g_ev_fork, cudaEventDisableTiming);
        cudaEventCreateWithFlags(&g_ev_join, cudaEventDisableTiming);
    }

    // fork: side stream joins the capture (or runs concurrently when eager)
    cudaEventRecord(g_ev_fork, 0);
    cudaStreamWaitEvent(g_s1, g_ev_fork, 0);

    // chain A (capture stream): pure 400 MB streaming zero
    k_zero<<<ZERO_BLOCKS, 256>>>((float4*)out);

    // chain B (side stream): prep -> edge
    k_prep<<<PREP_BLOCKS, 256, 0, g_s1>>>(embed, W1, ei);
    k_edge<<<EDGE_BLOCKS, 256, 0, g_s1>>>(b1, W2, b2);

    // join: sym needs both chains
    cudaEventRecord(g_ev_join, g_s1);
    cudaStreamWaitEvent(0, g_ev_join, 0);
    k_sym<<<SYM_BLOCKS, 256>>>(out);
}

// round 15
// speedup vs baseline: 1.4503x; 1.1094x over previous
#include <cuda_runtime.h>
#include <stdint.h>

// ---------------------------------------------------------------------------
// PGExplainer forward: masked_adj = adj * 0.5*(mask + mask^T)
// out[c,r] = cnt(c,r) * 0.5 * (S(c,r) + S(r,c)),  S = sum of sampled values
// Hash table: 16B AoS slots {key, sum(float), cnt, pad} -> probe + atomics +
// final reads are single-sector. Zero of d_out is split: 150MB rides in
// k_prep (absorbing its compute), 250MB in k_fused (absorbing edge latency).
// ---------------------------------------------------------------------------

#define N_NODES 10000
#define N_EDGES 640000
#define D_EMB   128
#define HID     64

#define OUT_ELEMS ((size_t)N_NODES * N_NODES)   // 1e8 floats = 400 MB
#define OUT_F4    (OUT_ELEMS / 4)               // 25,000,000 float4

#define HCAP  (1 << 21)                          // 2M slots x 16B = 32 MB
#define HMASK (HCAP - 1)

// ---- k_prep partition: [zero1 | gemm | decode+noise+clear] ----
#define Z1_BLOCKS       4688
#define Z1_PER          2000                     // f4 per zero block
#define Z1_TOTAL        ((size_t)Z1_BLOCKS * Z1_PER)   // 9,376,000 f4 = 150MB
#define PRE_HALF_BLOCKS 313
#define PRE_BLOCKS      (2 * PRE_HALF_BLOCKS)    // 626
#define DEC_BLOCKS      2500
#define PREP_BLOCKS     (Z1_BLOCKS + PRE_BLOCKS + DEC_BLOCKS)

// ---- k_fused (R7 interleaved shape): 20000 blocks, 32 edges each ----
#define FUSED_BLOCKS 20000
#define ZPB4F        782                         // ceil(15,624,000/20000)

// Scratch (device globals; hash table cleared in k_prep every call).
__device__ float g_A[N_NODES * HID];
__device__ float g_B[N_NODES * HID];
__device__ float g_noise[N_EDGES];
__device__ int2  g_ci[N_EDGES];
__device__ int   g_slot[N_EDGES];
__device__ int4  g_tab[HCAP];          // {key, sum(float bits), cnt, pad}

__device__ __forceinline__ uint32_t cell_hash(int key) {
    return ((uint32_t)key * 0x9E3779B1u) >> (32 - 21);
}

// Find-or-create slot for key (linear probing on the AoS .x field).
__device__ __forceinline__ uint32_t probe_slot(int key) {
    uint32_t h = cell_hash(key);
    while (true) {
        int k = __ldcg(&((const int*)g_tab)[h * 4]);
        if (k == key) break;
        if (k == -1) {
            int old = atomicCAS(&((int*)g_tab)[h * 4], -1, key);
            if (old == -1 || old == key) break;
        }
        h = (h + 1) & HMASK;
    }
    return h;
}

// ---------------------------------------------------------------------------
// threefry2x32 (JAX schedule), key = (0, 42); partitionable stream.
// ---------------------------------------------------------------------------
__device__ __forceinline__ uint32_t rotl32(uint32_t x, int d) {
    return (x << d) | (x >> (32 - d));
}

__device__ __forceinline__ void threefry2x32(uint32_t k0, uint32_t k1,
                                             uint32_t x0, uint32_t x1,
                                             uint32_t& o0, uint32_t& o1) {
    uint32_t ks0 = k0, ks1 = k1, ks2 = k0 ^ k1 ^ 0x1BD11BDAu;
#define TF_R4(a, b, c, d)                            \
    x0 += x1; x1 = rotl32(x1, a); x1 ^= x0;          \
    x0 += x1; x1 = rotl32(x1, b); x1 ^= x0;          \
    x0 += x1; x1 = rotl32(x1, c); x1 ^= x0;          \
    x0 += x1; x1 = rotl32(x1, d); x1 ^= x0;
    x0 += ks0; x1 += ks1;
    TF_R4(13, 15, 26, 6);  x0 += ks1; x1 += ks2 + 1u;
    TF_R4(17, 29, 16, 24); x0 += ks2; x1 += ks0 + 2u;
    TF_R4(13, 15, 26, 6);  x0 += ks0; x1 += ks1 + 3u;
    TF_R4(17, 29, 16, 24); x0 += ks1; x1 += ks2 + 4u;
    TF_R4(13, 15, 26, 6);  x0 += ks2; x1 += ks0 + 5u;
#undef TF_R4
    o0 = x0; o1 = x1;
}

__device__ __forceinline__ float noise_from_bits(uint32_t bits) {
    float u = __uint_as_float((bits >> 9) | 0x3f800000u) - 1.0f;   // [0,1)
    return logf(u) - log1pf(-u);   // u==0 -> -inf -> sigmoid -> 0
}

// ---------------------------------------------------------------------------
// K_prep: [0,4688) 150MB zero (first: store stream absorbs the compute) |
//         [4688,5314) GEMM tiles | [5314,7814) decode+noise+table clear.
// ---------------------------------------------------------------------------
__global__ void __launch_bounds__(256) k_prep(const float* __restrict__ embed,
                                              const float* __restrict__ W1,
                                              const void* __restrict__ ei_raw,
                                              float4* __restrict__ out) {
    __shared__ float es[32 * D_EMB];                  // 16 KB (GEMM blocks)
    __shared__ int   s_flag;

    if (blockIdx.x < Z1_BLOCKS) {
        // ---------------- zero slice 1 (exact coverage) ----------------
        const float4 z4 = make_float4(0.f, 0.f, 0.f, 0.f);
        size_t zbase = (size_t)blockIdx.x * Z1_PER;
        #pragma unroll
        for (int i = 0; i < 7; i++)
            __stcs(&out[zbase + threadIdx.x + i * 256], z4);
        if (threadIdx.x < Z1_PER - 7 * 256)
            __stcs(&out[zbase + threadIdx.x + 7 * 256], z4);
        return;
    }

    if (blockIdx.x < Z1_BLOCKS + PRE_BLOCKS) {
        // ---------------- per-node GEMM halves ----------------
        int pb   = blockIdx.x - Z1_BLOCKS;
        int half = pb >= PRE_HALF_BLOCKS;
        int nb   = pb - half * PRE_HALF_BLOCKS;
        int n0   = nb * 32;
        int hq   = threadIdx.x & 15;
        int gp   = threadIdx.x >> 4;

        const float4* emb4 = (const float4*)embed;
        size_t ebase = (size_t)n0 * (D_EMB / 4);
        float4* es4 = (float4*)es;
        #pragma unroll
        for (int i = 0; i < 4; i++) {
            size_t gidx = ebase + threadIdx.x + i * 256;
            if (gidx < (size_t)N_NODES * (D_EMB / 4))
                es4[threadIdx.x + i * 256] = emb4[gidx];
        }
        __syncthreads();

        const float4* W14 = (const float4*)(W1 + (size_t)half * D_EMB * HID);
        float4 a0 = make_float4(0.f, 0.f, 0.f, 0.f);
        float4 a1 = make_float4(0.f, 0.f, 0.f, 0.f);
        const float* er0 = es + (gp * 2)     * D_EMB;
        const float* er1 = es + (gp * 2 + 1) * D_EMB;
        #pragma unroll 8
        for (int d = 0; d < D_EMB; d++) {
            float4 w  = __ldg(&W14[d * 16 + hq]);
            float  e0 = er0[d];
            float  e1 = er1[d];
            a0.x = fmaf(e0, w.x, a0.x); a0.y = fmaf(e0, w.y, a0.y);
            a0.z = fmaf(e0, w.z, a0.z); a0.w = fmaf(e0, w.w, a0.w);
            a1.x = fmaf(e1, w.x, a1.x); a1.y = fmaf(e1, w.y, a1.y);
            a1.z = fmaf(e1, w.z, a1.z); a1.w = fmaf(e1, w.w, a1.w);
        }
        float4* dst = half ? (float4*)g_B : (float4*)g_A;
        int n = n0 + gp * 2;
        if (n < N_NODES)     dst[n * 16 + hq]       = a0;
        if (n + 1 < N_NODES) dst[(n + 1) * 16 + hq] = a1;
        return;
    }

    // ---------------- decode + noise + table clear ----------------
    {
        int bidx = blockIdx.x - (Z1_BLOCKS + PRE_BLOCKS);
        int e    = bidx * 256 + threadIdx.x;

        // inline dtype detect over a fixed 32KB window (same answer per block)
        if (threadIdx.x == 0) s_flag = 0;
        __syncthreads();
        const uint32_t* ew = (const uint32_t*)ei_raw;
        int nz = 0;
        #pragma unroll
        for (int i = 0; i < 16; i++)
            nz |= (ew[2 * (threadIdx.x + i * 256) + 1] != 0u);
        if (nz) s_flag = 1;
        __syncthreads();
        int is64 = s_flag ? 0 : 1;

        // AoS table clear: strided over the 640000 decode threads
        const int4 empty = make_int4(-1, 0, 0, 0);
        for (int i = e; i < HCAP; i += DEC_BLOCKS * 256)
            g_tab[i] = empty;

        if (e >= N_EDGES) return;
        int c, r;
        if (is64) {
            const long long* p = (const long long*)ei_raw;
            c = (int)p[e];
            r = (int)p[N_EDGES + e];
        } else {
            const int* p = (const int*)ei_raw;
            c = p[e];
            r = p[N_EDGES + e];
        }
        c = min(max(c, 0), N_NODES - 1);
        r = min(max(r, 0), N_NODES - 1);
        g_ci[e] = make_int2(c, r);

        uint32_t o0, o1;
        threefry2x32(0u, 42u, 0u, (uint32_t)e, o0, o1);
        g_noise[e] = noise_from_bits(o0 ^ o1);
    }
}

// ---------------------------------------------------------------------------
// K_fused (R7 proven interleave): EVERY block zeroes a 782-float4 slab of the
// remaining 250MB AND processes 32 edges (8-lane groups, single insert).
// ---------------------------------------------------------------------------
__global__ void __launch_bounds__(256) k_fused(const float* __restrict__ b1,
                                               const float* __restrict__ W2,
                                               const float* __restrict__ b2,
                                               float4* __restrict__ out) {
    // ---- zero slab (bounds-checked tail) ----
    const float4 z4 = make_float4(0.f, 0.f, 0.f, 0.f);
    size_t zbase = Z1_TOTAL + (size_t)blockIdx.x * ZPB4F;
    #pragma unroll
    for (int i = 0; i < 3; i++) {
        size_t idx = zbase + threadIdx.x + i * 256;
        if (idx < OUT_F4) __stcs(&out[idx], z4);
    }
    if (threadIdx.x < ZPB4F - 3 * 256) {
        size_t idx = zbase + threadIdx.x + 3 * 256;
        if (idx < OUT_F4) __stcs(&out[idx], z4);
    }

    // ---- edge work: 32 edges/block, one 8-lane group per edge ----
    int warp = threadIdx.x >> 5;
    int lane = threadIdx.x & 31;
    int grp  = lane >> 3;
    int l8   = lane & 7;
    int e    = blockIdx.x * 32 + warp * 4 + grp;

    int2 cr = g_ci[e];

    const float4* b14 = (const float4*)b1;
    const float4* w24 = (const float4*)W2;
    float4 b1a = __ldg(&b14[l8 * 2]);
    float4 b1b = __ldg(&b14[l8 * 2 + 1]);
    float4 w2a = __ldg(&w24[l8 * 2]);
    float4 w2b = __ldg(&w24[l8 * 2 + 1]);

    const float4* A4 = (const float4*)g_A;
    const float4* B4 = (const float4*)g_B;
    float4 av0 = A4[cr.x * 16 + l8 * 2];
    float4 av1 = A4[cr.x * 16 + l8 * 2 + 1];
    float4 bv0 = B4[cr.y * 16 + l8 * 2];
    float4 bv1 = B4[cr.y * 16 + l8 * 2 + 1];

    float s;
    s  = fmaxf(av0.x + bv0.x + b1a.x, 0.f) * w2a.x;
    s += fmaxf(av0.y + bv0.y + b1a.y, 0.f) * w2a.y;
    s += fmaxf(av0.z + bv0.z + b1a.z, 0.f) * w2a.z;
    s += fmaxf(av0.w + bv0.w + b1a.w, 0.f) * w2a.w;
    s += fmaxf(av1.x + bv1.x + b1b.x, 0.f) * w2b.x;
    s += fmaxf(av1.y + bv1.y + b1b.y, 0.f) * w2b.y;
    s += fmaxf(av1.z + bv1.z + b1b.z, 0.f) * w2b.z;
    s += fmaxf(av1.w + bv1.w + b1b.w, 0.f) * w2b.w;

    s += __shfl_xor_sync(0xffffffffu, s, 1);
    s += __shfl_xor_sync(0xffffffffu, s, 2);
    s += __shfl_xor_sync(0xffffffffu, s, 4);

    if (l8 == 0) {
        float x = g_noise[e] + s + __ldg(&b2[0]);
        float v = 1.0f / (1.0f + expf(-x));   // sigmoid; -inf -> 0 exactly

        uint32_t h = probe_slot(cr.x * N_NODES + cr.y);
        atomicAdd((float*)&((int*)g_tab)[h * 4 + 1], v);
        atomicAdd(&((int*)g_tab)[h * 4 + 2], 1);
        g_slot[e] = (int)h;
    }
}

// ---------------------------------------------------------------------------
// K_sym: 1 edge/thread (2500 blocks). AoS slot -> single-sector reads:
//   out[c,r] = cnt * 0.5 * (S + S_transpose)   (idempotent streaming store)
// ---------------------------------------------------------------------------
__global__ void __launch_bounds__(256) k_sym(float* __restrict__ out) {
    int e = blockIdx.x * blockDim.x + threadIdx.x;
    if (e >= N_EDGES) return;
    int2 cr  = __ldg(&g_ci[e]);
    int slot = __ldg(&g_slot[e]);

    int4 own = __ldcg(&g_tab[slot]);               // {key, S, cnt, pad}
    float S  = __int_as_float(own.y);
    int  cnt = own.z;

    int tkey = cr.y * N_NODES + cr.x;
    float ST = 0.0f;
    uint32_t h = cell_hash(tkey);
    while (true) {
        int4 sl = __ldcg(&g_tab[h]);               // one sector: key+sum
        if (sl.x == tkey) { ST = __int_as_float(sl.y); break; }
        if (sl.x == -1) break;
        h = (h + 1) & HMASK;
    }
    __stcs(&out[(size_t)cr.x * N_NODES + cr.y], (float)cnt * 0.5f * (S + ST));
}

// ---------------------------------------------------------------------------
extern "C" void kernel_launch(void* const* d_in, const int* in_sizes, int n_in,
                              void* d_out, int out_size) {
    const float* embed = (const float*)d_in[0];
    const void*  ei    = d_in[1];
    const float* W1    = (const float*)d_in[2];
    const float* b1    = (const float*)d_in[3];
    const float* W2    = (const float*)d_in[4];
    const float* b2    = (const float*)d_in[5];
    float*       out   = (float*)d_out;

    // 1. prep: 150MB zero (first) | GEMM | decode+noise+AoS table clear
    k_prep<<<PREP_BLOCKS, 256>>>(embed, W1, ei, (float4*)out);

    // 2. fused: 250MB zero + edge MLP/sample/insert (R7 interleave)
    k_fused<<<FUSED_BLOCKS, 256>>>(b1, W2, b2, (float4*)out);

    // 3. symmetrize -> idempotent streaming stores
    k_sym<<<(N_EDGES + 255) / 256, 256>>>(out);
}

// round 16
// speedup vs baseline: 1.7257x; 1.1899x over previous
#include <cuda_runtime.h>
#include <cuda_fp16.h>
#include <stdint.h>

// ---------------------------------------------------------------------------
// PGExplainer forward: masked_adj = adj * 0.5*(mask + mask^T)
// out[c,r] = cnt(c,r) * 0.5 * (S(c,r) + S(r,c)),  S = sum of sampled values
// A/B node tables stored fp16 (one 128B line per node per table) to halve
// the dominant L2 gather traffic. Hash table: 16B AoS {key, sum, cnt, pad}.
// ---------------------------------------------------------------------------

#define N_NODES 10000
#define N_EDGES 640000
#define D_EMB   128
#define HID     64

#define OUT_ELEMS ((size_t)N_NODES * N_NODES)   // 1e8 floats = 400 MB
#define OUT_F4    (OUT_ELEMS / 4)               // 25,000,000 float4

#define HCAP  (1 << 21)                          // 2M slots x 16B = 32 MB
#define HMASK (HCAP - 1)

// ---- k_prep (R8 shape): [gemm | decode+noise+clear] ----
#define PRE_HALF_BLOCKS 313
#define PRE_BLOCKS      (2 * PRE_HALF_BLOCKS)    // 626
#define DEC_BLOCKS      2500
#define PREP_BLOCKS     (PRE_BLOCKS + DEC_BLOCKS)

// ---- k_fused (R7 interleave): 20000 blocks, 1250 f4 zero + 32 edges ----
#define FUSED_BLOCKS 20000
#define ZPB4         1250                        // 20000*1250 = 25M exact

// Scratch (device globals; hash table cleared in k_prep every call).
__device__ __half g_Ah[N_NODES * HID];   // 1.25 MB, row = 128 B
__device__ __half g_Bh[N_NODES * HID];
__device__ float  g_noise[N_EDGES];
__device__ int2   g_ci[N_EDGES];
__device__ int    g_slot[N_EDGES];
__device__ int4   g_tab[HCAP];           // {key, sum(float bits), cnt, pad}

__device__ __forceinline__ uint32_t cell_hash(int key) {
    return ((uint32_t)key * 0x9E3779B1u) >> (32 - 21);
}

__device__ __forceinline__ uint32_t probe_slot(int key) {
    uint32_t h = cell_hash(key);
    while (true) {
        int k = __ldcg(&((const int*)g_tab)[h * 4]);
        if (k == key) break;
        if (k == -1) {
            int old = atomicCAS(&((int*)g_tab)[h * 4], -1, key);
            if (old == -1 || old == key) break;
        }
        h = (h + 1) & HMASK;
    }
    return h;
}

// ---------------------------------------------------------------------------
// threefry2x32 (JAX schedule), key = (0, 42); partitionable stream.
// ---------------------------------------------------------------------------
__device__ __forceinline__ uint32_t rotl32(uint32_t x, int d) {
    return (x << d) | (x >> (32 - d));
}

__device__ __forceinline__ void threefry2x32(uint32_t k0, uint32_t k1,
                                             uint32_t x0, uint32_t x1,
                                             uint32_t& o0, uint32_t& o1) {
    uint32_t ks0 = k0, ks1 = k1, ks2 = k0 ^ k1 ^ 0x1BD11BDAu;
#define TF_R4(a, b, c, d)                            \
    x0 += x1; x1 = rotl32(x1, a); x1 ^= x0;          \
    x0 += x1; x1 = rotl32(x1, b); x1 ^= x0;          \
    x0 += x1; x1 = rotl32(x1, c); x1 ^= x0;          \
    x0 += x1; x1 = rotl32(x1, d); x1 ^= x0;
    x0 += ks0; x1 += ks1;
    TF_R4(13, 15, 26, 6);  x0 += ks1; x1 += ks2 + 1u;
    TF_R4(17, 29, 16, 24); x0 += ks2; x1 += ks0 + 2u;
    TF_R4(13, 15, 26, 6);  x0 += ks0; x1 += ks1 + 3u;
    TF_R4(17, 29, 16, 24); x0 += ks1; x1 += ks2 + 4u;
    TF_R4(13, 15, 26, 6);  x0 += ks2; x1 += ks0 + 5u;
#undef TF_R4
    o0 = x0; o1 = x1;
}

__device__ __forceinline__ float noise_from_bits(uint32_t bits) {
    float u = __uint_as_float((bits >> 9) | 0x3f800000u) - 1.0f;   // [0,1)
    return logf(u) - log1pf(-u);   // u==0 -> -inf -> sigmoid -> 0
}

// ---------------------------------------------------------------------------
// K_prep: [0,626) GEMM tiles (fp32 compute, fp16 store) |
//         [626,3126) decode+clamp+noise + AoS table clear.
// ---------------------------------------------------------------------------
__global__ void __launch_bounds__(256) k_prep(const float* __restrict__ embed,
                                              const float* __restrict__ W1,
                                              const void* __restrict__ ei_raw) {
    __shared__ float es[32 * D_EMB];                  // 16 KB
    __shared__ int   s_flag;

    if (blockIdx.x < PRE_BLOCKS) {
        int half = blockIdx.x >= PRE_HALF_BLOCKS;
        int nb   = blockIdx.x - half * PRE_HALF_BLOCKS;
        int n0   = nb * 32;
        int hq   = threadIdx.x & 15;                  // h-quad: h = hq*4
        int gp   = threadIdx.x >> 4;                  // node-pair

        const float4* emb4 = (const float4*)embed;
        size_t ebase = (size_t)n0 * (D_EMB / 4);
        float4* es4 = (float4*)es;
        #pragma unroll
        for (int i = 0; i < 4; i++) {
            size_t gidx = ebase + threadIdx.x + i * 256;
            if (gidx < (size_t)N_NODES * (D_EMB / 4))
                es4[threadIdx.x + i * 256] = emb4[gidx];
        }
        __syncthreads();

        const float4* W14 = (const float4*)(W1 + (size_t)half * D_EMB * HID);
        float4 a0 = make_float4(0.f, 0.f, 0.f, 0.f);
        float4 a1 = make_float4(0.f, 0.f, 0.f, 0.f);
        const float* er0 = es + (gp * 2)     * D_EMB;
        const float* er1 = es + (gp * 2 + 1) * D_EMB;
        #pragma unroll 8
        for (int d = 0; d < D_EMB; d++) {
            float4 w  = __ldg(&W14[d * 16 + hq]);
            float  e0 = er0[d];
            float  e1 = er1[d];
            a0.x = fmaf(e0, w.x, a0.x); a0.y = fmaf(e0, w.y, a0.y);
            a0.z = fmaf(e0, w.z, a0.z); a0.w = fmaf(e0, w.w, a0.w);
            a1.x = fmaf(e1, w.x, a1.x); a1.y = fmaf(e1, w.y, a1.y);
            a1.z = fmaf(e1, w.z, a1.z); a1.w = fmaf(e1, w.w, a1.w);
        }
        __half* base = half ? g_Bh : g_Ah;
        uint2* dst = (uint2*)base;                    // 4 halfs per uint2
        int n = n0 + gp * 2;
        if (n < N_NODES) {
            __half2 p0 = __floats2half2_rn(a0.x, a0.y);
            __half2 p1 = __floats2half2_rn(a0.z, a0.w);
            uint2 u;
            u.x = *(uint32_t*)&p0;
            u.y = *(uint32_t*)&p1;
            dst[n * 16 + hq] = u;                     // row = 64 halfs = 16 uint2
        }
        if (n + 1 < N_NODES) {
            __half2 p0 = __floats2half2_rn(a1.x, a1.y);
            __half2 p1 = __floats2half2_rn(a1.z, a1.w);
            uint2 u;
            u.x = *(uint32_t*)&p0;
            u.y = *(uint32_t*)&p1;
            dst[(n + 1) * 16 + hq] = u;
        }
        return;
    }

    // ---------------- decode + noise + AoS table clear ----------------
    {
        int bidx = blockIdx.x - PRE_BLOCKS;
        int e    = bidx * 256 + threadIdx.x;

        // inline dtype detect over a fixed 32KB window (same answer per block)
        if (threadIdx.x == 0) s_flag = 0;
        __syncthreads();
        const uint32_t* ew = (const uint32_t*)ei_raw;
        int nz = 0;
        #pragma unroll
        for (int i = 0; i < 16; i++)
            nz |= (ew[2 * (threadIdx.x + i * 256) + 1] != 0u);
        if (nz) s_flag = 1;
        __syncthreads();
        int is64 = s_flag ? 0 : 1;

        // AoS table clear (strided over 640000 decode threads, ~3.3 iters)
        const int4 empty = make_int4(-1, 0, 0, 0);
        for (int i = e; i < HCAP; i += DEC_BLOCKS * 256)
            g_tab[i] = empty;

        if (e >= N_EDGES) return;
        int c, r;
        if (is64) {
            const long long* p = (const long long*)ei_raw;
            c = (int)p[e];
            r = (int)p[N_EDGES + e];
        } else {
            const int* p = (const int*)ei_raw;
            c = p[e];
            r = p[N_EDGES + e];
        }
        c = min(max(c, 0), N_NODES - 1);
        r = min(max(r, 0), N_NODES - 1);
        g_ci[e] = make_int2(c, r);

        uint32_t o0, o1;
        threefry2x32(0u, 42u, 0u, (uint32_t)e, o0, o1);
        g_noise[e] = noise_from_bits(o0 ^ o1);
    }
}

// ---------------------------------------------------------------------------
// K_fused (R7 interleave): EVERY block zeroes a 1250-float4 slab of d_out AND
// processes 32 edges. Per edge: one 128B A row + one 128B B row (fp16),
// one int4 load per lane. Single hash insert.
// ---------------------------------------------------------------------------
__global__ void __launch_bounds__(256) k_fused(const float* __restrict__ b1,
                                               const float* __restrict__ W2,
                                               const float* __restrict__ b2,
                                               float4* __restrict__ out) {
    // ---- zero slab (exact coverage) ----
    const float4 z4 = make_float4(0.f, 0.f, 0.f, 0.f);
    size_t zbase = (size_t)blockIdx.x * ZPB4;
    #pragma unroll
    for (int i = 0; i < 4; i++)
        __stcs(&out[zbase + threadIdx.x + i * 256], z4);
    if (threadIdx.x < ZPB4 - 1024)
        __stcs(&out[zbase + threadIdx.x + 1024], z4);

    // ---- 32 edges/block: one 8-lane group per edge ----
    int warp = threadIdx.x >> 5;
    int lane = threadIdx.x & 31;
    int grp  = lane >> 3;
    int l8   = lane & 7;           // handles h in [l8*8, l8*8+8)
    int e    = blockIdx.x * 32 + warp * 4 + grp;

    int2 cr = g_ci[e];

    const float4* b14 = (const float4*)b1;
    const float4* w24 = (const float4*)W2;
    float4 b1a = __ldg(&b14[l8 * 2]);        // h = l8*8 .. +4
    float4 b1b = __ldg(&b14[l8 * 2 + 1]);    // h = l8*8+4 .. +8
    float4 w2a = __ldg(&w24[l8 * 2]);
    float4 w2b = __ldg(&w24[l8 * 2 + 1]);

    // fp16 rows: 64 halfs = 8 int4 per node; lane l8 takes int4 #l8
    const int4* A4 = (const int4*)g_Ah;
    const int4* B4 = (const int4*)g_Bh;
    int4 ar = A4[cr.x * 8 + l8];
    int4 br = B4[cr.y * 8 + l8];

    const __half2* ah = (const __half2*)&ar;   // 4 half2 = 8 values
    const __half2* bh = (const __half2*)&br;
    float2 a01 = __half22float2(ah[0]);
    float2 a23 = __half22float2(ah[1]);
    float2 a45 = __half22float2(ah[2]);
    float2 a67 = __half22float2(ah[3]);
    float2 c01 = __half22float2(bh[0]);
    float2 c23 = __half22float2(bh[1]);
    float2 c45 = __half22float2(bh[2]);
    float2 c67 = __half22float2(bh[3]);

    float s;
    s  = fmaxf(a01.x + c01.x + b1a.x, 0.f) * w2a.x;
    s += fmaxf(a01.y + c01.y + b1a.y, 0.f) * w2a.y;
    s += fmaxf(a23.x + c23.x + b1a.z, 0.f) * w2a.z;
    s += fmaxf(a23.y + c23.y + b1a.w, 0.f) * w2a.w;
    s += fmaxf(a45.x + c45.x + b1b.x, 0.f) * w2b.x;
    s += fmaxf(a45.y + c45.y + b1b.y, 0.f) * w2b.y;
    s += fmaxf(a67.x + c67.x + b1b.z, 0.f) * w2b.z;
    s += fmaxf(a67.y + c67.y + b1b.w, 0.f) * w2b.w;

    // reduce across the 8 lanes of this edge group
    s += __shfl_xor_sync(0xffffffffu, s, 1);
    s += __shfl_xor_sync(0xffffffffu, s, 2);
    s += __shfl_xor_sync(0xffffffffu, s, 4);

    if (l8 == 0) {
        float x = g_noise[e] + s + __ldg(&b2[0]);
        float v = 1.0f / (1.0f + expf(-x));   // sigmoid; -inf -> 0 exactly

        uint32_t h = probe_slot(cr.x * N_NODES + cr.y);
        atomicAdd((float*)&((int*)g_tab)[h * 4 + 1], v);
        atomicAdd(&((int*)g_tab)[h * 4 + 2], 1);
        g_slot[e] = (int)h;
    }
}

// ---------------------------------------------------------------------------
// K_sym: 1 edge/thread. AoS slot reads are single-sector:
//   out[c,r] = cnt * 0.5 * (S + S_transpose)   (idempotent streaming store)
// ---------------------------------------------------------------------------
__global__ void __launch_bounds__(256) k_sym(float* __restrict__ out) {
    int e = blockIdx.x * blockDim.x + threadIdx.x;
    if (e >= N_EDGES) return;
    int2 cr  = __ldg(&g_ci[e]);
    int slot = __ldg(&g_slot[e]);

    int4 own = __ldcg(&g_tab[slot]);               // {key, S, cnt, pad}
    float S  = __int_as_float(own.y);
    int  cnt = own.z;

    int tkey = cr.y * N_NODES + cr.x;
    float ST = 0.0f;
    uint32_t h = cell_hash(tkey);
    while (true) {
        int4 sl = __ldcg(&g_tab[h]);
        if (sl.x == tkey) { ST = __int_as_float(sl.y); break; }
        if (sl.x == -1) break;
        h = (h + 1) & HMASK;
    }
    __stcs(&out[(size_t)cr.x * N_NODES + cr.y], (float)cnt * 0.5f * (S + ST));
}

// ---------------------------------------------------------------------------
extern "C" void kernel_launch(void* const* d_in, const int* in_sizes, int n_in,
                              void* d_out, int out_size) {
    const float* embed = (const float*)d_in[0];
    const void*  ei    = d_in[1];
    const float* W1    = (const float*)d_in[2];
    const float* b1    = (const float*)d_in[3];
    const float* W2    = (const float*)d_in[4];
    const float* b2    = (const float*)d_in[5];
    float*       out   = (float*)d_out;

    // 1. prep: GEMM (fp16 tables) | decode+noise+AoS table clear
    k_prep<<<PREP_BLOCKS, 256>>>(embed, W1, ei);

    // 2. fused: 400 MB zero + edge MLP/sample/insert (R7 interleave, fp16 gathers)
    k_fused<<<FUSED_BLOCKS, 256>>>(b1, W2, b2, (float4*)out);

    // 3. symmetrize -> idempotent streaming stores
    k_sym<<<(N_EDGES + 255) / 256, 256>>>(out);
}